// round 1
// baseline (speedup 1.0000x reference)
#include <cuda_runtime.h>
#include <math.h>

#define B_   4
#define CIN  32
#define HID  32
#define CO   64
#define T_   31
#define H_   96
#define W_   96
#define HW   (H_*W_)          /* 9216 */
#define NELEM (B_*HID*T_*HW)  /* 36,569,088 */

// Scratch (device globals; no runtime allocation allowed)
__device__ float g_Z[NELEM];          // tanh gate   [B][C][T][H][W]
__device__ float g_F[NELEM];          // sigmoid gate[B][C][T][H][W]
__device__ float g_Hq[NELEM];         // h_time      [B][H][W][C][T]
__device__ float g_wT[CO*CIN*27];     // weights transposed: [ci*27+tap][co]

// ---------------------------------------------------------------------------
// Weight transpose: OIDHW [co][ci][27] -> [ci*27+tap][co]
// ---------------------------------------------------------------------------
__global__ void wtrans_kernel(const float* __restrict__ w) {
    int i = blockIdx.x * 256 + threadIdx.x;
    if (i >= CO*CIN*27) return;
    int co = i / (CIN*27);
    int k  = i % (CIN*27);
    g_wT[k*CO + co] = w[i];
}

// ---------------------------------------------------------------------------
// Conv3d 3x3x3 SAME + bias + tanh/sigmoid -> g_Z, g_F
// Block: 256 threads, tile = 8h x 32w x 64co for fixed (b,t).
// Thread: cg = tid>>5 (co group of 8), s = tid&31 -> (hq = s>>3, wq = s&7)
// Register tile: 2(h) x 4(w contiguous) x 8(co) = 64 accumulators.
// smem: input chunk [8ci][3t][10h][35w(pad)] + weights [216k][64co]
// ---------------------------------------------------------------------------
#define SM_IN (8*3*10*35)   /* 8400 floats */
#define SM_W  (8*27*64)     /* 13824 floats */

__global__ __launch_bounds__(256, 2)
void conv_kernel(const float* __restrict__ in, const float* __restrict__ bias) {
    extern __shared__ float smem[];
    float* s_in = smem;            // [(cil*3+tz)*10 + y]*35 + x
    float* s_w  = smem + SM_IN;    // [k*64 + co]

    const int w0 = blockIdx.x * 32;
    const int h0 = blockIdx.y * 8;
    const int bz = blockIdx.z;
    const int b  = bz / T_;
    const int t  = bz % T_;
    const int tid = threadIdx.x;
    const int cg = tid >> 5;
    const int s  = tid & 31;
    const int wq = s & 7;
    const int hq = s >> 3;

    float acc[2][4][8];
    #pragma unroll
    for (int a = 0; a < 2; a++)
        #pragma unroll
        for (int j = 0; j < 4; j++)
            #pragma unroll
            for (int q = 0; q < 8; q++) acc[a][j][q] = 0.f;

    for (int cig = 0; cig < 4; cig++) {
        __syncthreads();
        // ---- load input halo tile (zero-padded at borders) ----
        for (int li = tid; li < 8*3*10*34; li += 256) {
            int x = li % 34; int r = li / 34;
            int y = r % 10;  r /= 10;
            int tz = r % 3;  int cil = r / 3;
            int ci = cig*8 + cil;
            int tt = t + tz - 1;
            int gh = h0 + y - 1;
            int gw = w0 + x - 1;
            float v = 0.f;
            if (tt >= 0 && tt < T_ && gh >= 0 && gh < H_ && gw >= 0 && gw < W_)
                v = in[((size_t)((b*CIN + ci)*T_ + tt)*H_ + gh)*W_ + gw];
            s_in[((cil*3 + tz)*10 + y)*35 + x] = v;
        }
        // ---- load weight chunk (contiguous, float4) ----
        {
            const float4* gw4 = (const float4*)(g_wT + cig*SM_W);
            float4* sw4 = (float4*)s_w;
            for (int li = tid; li < SM_W/4; li += 256) sw4[li] = gw4[li];
        }
        __syncthreads();
        // ---- compute ----
        for (int cil = 0; cil < 8; cil++) {
            #pragma unroll
            for (int kt = 0; kt < 3; kt++) {
                const float* pin = s_in + (cil*3 + kt)*350;
                #pragma unroll
                for (int kh = 0; kh < 3; kh++) {
                    #pragma unroll
                    for (int kw = 0; kw < 3; kw++) {
                        const int k = cil*27 + (kt*3 + kh)*3 + kw;
                        float4 wa = *(const float4*)(s_w + k*64 + cg*8);
                        float4 wb = *(const float4*)(s_w + k*64 + cg*8 + 4);
                        float wv[8] = {wa.x, wa.y, wa.z, wa.w, wb.x, wb.y, wb.z, wb.w};
                        float xv[2][4];
                        #pragma unroll
                        for (int hh = 0; hh < 2; hh++)
                            #pragma unroll
                            for (int j = 0; j < 4; j++)
                                xv[hh][j] = pin[(hq + 4*hh + kh)*35 + wq*4 + kw + j];
                        #pragma unroll
                        for (int hh = 0; hh < 2; hh++)
                            #pragma unroll
                            for (int j = 0; j < 4; j++)
                                #pragma unroll
                                for (int q = 0; q < 8; q++)
                                    acc[hh][j][q] += xv[hh][j] * wv[q];
                    }
                }
            }
        }
    }

    // ---- epilogue: bias + activation, float4 coalesced stores ----
    #pragma unroll
    for (int q = 0; q < 8; q++) {
        const int co = cg*8 + q;
        const float bb = bias[co];
        #pragma unroll
        for (int hh = 0; hh < 2; hh++) {
            const int h = h0 + hq + 4*hh;
            const int w = w0 + wq*4;
            float g0 = acc[hh][0][q] + bb;
            float g1 = acc[hh][1][q] + bb;
            float g2 = acc[hh][2][q] + bb;
            float g3 = acc[hh][3][q] + bb;
            if (co < HID) {
                float4 v = make_float4(tanhf(g0), tanhf(g1), tanhf(g2), tanhf(g3));
                *(float4*)(g_Z + ((size_t)((b*HID + co)*T_ + t)*H_ + h)*W_ + w) = v;
            } else {
                const int c2 = co - HID;
                float4 v = make_float4(1.f/(1.f + __expf(-g0)),
                                       1.f/(1.f + __expf(-g1)),
                                       1.f/(1.f + __expf(-g2)),
                                       1.f/(1.f + __expf(-g3)));
                *(float4*)(g_F + ((size_t)((b*HID + c2)*T_ + t)*H_ + h)*W_ + w) = v;
            }
        }
    }
}

// ---------------------------------------------------------------------------
// Gated recurrence h_t = f*h + (1-f)*z, transposing to [B][H][W][C][T]
// Block: 256 threads = 32c x 8w, for fixed (b,h,w-octet).
// Reads coalesced along w; writes staged via smem -> one fully-contiguous
// 7936-float run per block.
// ---------------------------------------------------------------------------
__global__ __launch_bounds__(256)
void recur_kernel() {
    __shared__ float s[8*993];  // [wi][c*31 + t], stride 993 (pad)
    const int w0 = blockIdx.x * 8;
    const int h  = blockIdx.y;
    const int b  = blockIdx.z;
    const int tid = threadIdx.x;
    const int c  = tid >> 3;
    const int wi = tid & 7;

    size_t base = (size_t)((b*HID + c)*T_)*HW + h*W_ + w0 + wi;
    float hs = 0.f;
    float* srow = s + wi*993 + c*31;
    for (int t = 0; t < T_; t++) {
        float z = g_Z[base + (size_t)t*HW];
        float f = g_F[base + (size_t)t*HW];
        hs = f*hs + (1.f - f)*z;
        srow[t] = hs;
    }
    __syncthreads();
    size_t ob = (size_t)((b*H_ + h)*W_ + w0) * (HID*T_);
    for (int li = tid; li < 8*992; li += 256)
        g_Hq[ob + li] = s[(li/992)*993 + (li%992)];
}

// ---------------------------------------------------------------------------
// Channel attention per pixel. Block: 256 thr (8 warps) x 32 pixels
// (4 per warp, sequential). smem: qh for 32 pixels, stride 993 (conflict-free).
// Gram symmetry: column softmax stats == each lane's own-row stats ->
// only 2 shuffles per column.
// ---------------------------------------------------------------------------
__global__ __launch_bounds__(256, 1)
void attn_kernel(const float* __restrict__ gamma, float* __restrict__ out) {
    extern __shared__ float sq[];   // 32 * 993 floats
    const int w0 = blockIdx.x * 32;
    const int h  = blockIdx.y;
    const int b  = blockIdx.z;
    const int tid = threadIdx.x;

    // coalesced float4 load of 32 pixels' qh (contiguous in g_Hq)
    size_t baseq = (size_t)((b*H_ + h)*W_ + w0) * (HID*T_);
    const float4* src4 = (const float4*)(g_Hq + baseq);
    for (int i4 = tid; i4 < (32*992)/4; i4 += 256) {
        float4 v = src4[i4];
        int w = i4 / 248;
        int r = (i4 % 248) * 4;
        float* d = sq + w*993 + r;
        d[0] = v.x; d[1] = v.y; d[2] = v.z; d[3] = v.w;
    }
    __syncthreads();

    const float gam = gamma[0];
    const int lane = tid & 31;
    const int wid  = tid >> 5;

    for (int it = 0; it < 4; it++) {
        const int wi = wid*4 + it;
        float* q = sq + wi*993;

        float qr[31];
        #pragma unroll
        for (int t = 0; t < 31; t++) qr[t] = q[lane*31 + t];

        float sc[32];
        #pragma unroll
        for (int d = 0; d < 32; d++) {
            float a = 0.f;
            #pragma unroll
            for (int t = 0; t < 31; t++) a += qr[t] * q[d*31 + t];
            sc[d] = a;
        }

        // own-row stats == column stats (Gram matrix is symmetric)
        float mrow = sc[0];
        #pragma unroll
        for (int d = 1; d < 32; d++) mrow = fmaxf(mrow, sc[d]);
        float srow = 0.f;
        #pragma unroll
        for (int d = 0; d < 32; d++) srow += __expf(sc[d] - mrow);

        float ah[31];
        #pragma unroll
        for (int t = 0; t < 31; t++) ah[t] = 0.f;
        #pragma unroll
        for (int d = 0; d < 32; d++) {
            float mc = __shfl_sync(0xffffffffu, mrow, d);
            float ssc = __shfl_sync(0xffffffffu, srow, d);
            float a = __expf(sc[d] - mc) / ssc * 0.17677669529663687f; // 1/sqrt(32)
            #pragma unroll
            for (int t = 0; t < 31; t++) ah[t] += a * q[d*31 + t];
        }

        __syncwarp();
        #pragma unroll
        for (int t = 0; t < 31; t++) q[lane*31 + t] = gam*ah[t] + qr[t];
    }
    __syncthreads();

    // coalesced store back to [B][C][T][H][W]
    for (int i = tid; i < 32*992; i += 256) {
        int w  = i & 31;
        int ct = i >> 5;
        int c  = ct / 31;
        int t  = ct % 31;
        out[((size_t)((b*HID + c)*T_ + t)*H_ + h)*W_ + w0 + w] = sq[w*993 + c*31 + t];
    }
}

// ---------------------------------------------------------------------------
extern "C" void kernel_launch(void* const* d_in, const int* in_sizes, int n_in,
                              void* d_out, int out_size) {
    const float* input  = (const float*)d_in[0];
    const float* conv_w = (const float*)d_in[1];
    const float* conv_b = (const float*)d_in[2];
    const float* gamma  = (const float*)d_in[3];
    float* out = (float*)d_out;

    wtrans_kernel<<<(CO*CIN*27 + 255)/256, 256>>>(conv_w);

    cudaFuncSetAttribute(conv_kernel, cudaFuncAttributeMaxDynamicSharedMemorySize,
                         (SM_IN + SM_W)*4);
    dim3 cgrid(W_/32, H_/8, B_*T_);
    conv_kernel<<<cgrid, 256, (SM_IN + SM_W)*4>>>(input, conv_b);

    dim3 rgrid(W_/8, H_, B_);
    recur_kernel<<<rgrid, 256>>>();

    cudaFuncSetAttribute(attn_kernel, cudaFuncAttributeMaxDynamicSharedMemorySize,
                         32*993*4);
    dim3 agrid(W_/32, H_, B_);
    attn_kernel<<<agrid, 256, 32*993*4>>>(gamma, out);
}

// round 2
// speedup vs baseline: 2.0859x; 2.0859x over previous
#include <cuda_runtime.h>
#include <cuda_bf16.h>
#include <math.h>

#define B_   4
#define CIN  32
#define HID  32
#define T_   31
#define H_   96
#define W_   96
#define HW   (H_*W_)          /* 9216 */
#define CTHW ((size_t)T_*HW)  /* per-channel stride 285696 */
#define NELEM (B_*HID*T_*HW)

// Scratch (device globals; no runtime allocation)
__device__ float g_Z[NELEM];              // tanh gate   [B][C][T][H][W]
__device__ float g_F[NELEM];              // sigmoid gate[B][C][T][H][W]
__device__ unsigned g_wfrag[4*14*2*8*32*2]; // weight fragments, HMMA B-order

// ---------------------------------------------------------------------------
// Weight fragment prep: conv_w [co=64][ci=32][tap=27] -> bf16 hi/lo fragments
// k ordering: k = tap*8 + ci_local (tap padded to 28, tap 27 == zero)
// word idx = cig*14336 + s*1024 + split*512 + nt*64 + lane*2 + r
// B-fragment mapping (m16n8k16 row.col): reg r: k = s*16 + (lane&3)*2 + r*8 + e,
//                                        n  = nt*8 + (lane>>2)
// ---------------------------------------------------------------------------
__global__ void wfrag_kernel(const float* __restrict__ w) {
    int idx = blockIdx.x * 256 + threadIdx.x;
    if (idx >= 4*14336) return;
    int r    = idx & 1;
    int lane = (idx >> 1) & 31;
    int nt   = (idx >> 6) & 7;
    int split= (idx >> 9) & 1;
    int rest = idx >> 10;
    int s    = rest % 14;
    int cig  = rest / 14;
    int q    = lane & 3;
    int n    = nt*8 + (lane >> 2);     // co
    unsigned word = 0;
    for (int e = 0; e < 2; e++) {
        int k   = s*16 + q*2 + r*8 + e;
        int cil = k & 7;
        int tap = k >> 3;
        float val = 0.f;
        if (tap < 27) val = w[(n*CIN + (cig*8 + cil))*27 + tap];
        __nv_bfloat16 hb = __float2bfloat16_rn(val);
        __nv_bfloat16 res = hb;
        if (split) res = __float2bfloat16_rn(val - __bfloat162float(hb));
        word |= ((unsigned)__bfloat16_as_ushort(res)) << (16*e);
    }
    g_wfrag[idx] = word;
}

// ---------------------------------------------------------------------------
// helpers
// ---------------------------------------------------------------------------
__device__ __forceinline__ void split_pack(float x0, float x1,
                                           unsigned &hi, unsigned &lo) {
    __nv_bfloat16 h0 = __float2bfloat16_rn(x0);
    __nv_bfloat16 h1 = __float2bfloat16_rn(x1);
    float r0 = x0 - __bfloat162float(h0);
    float r1 = x1 - __bfloat162float(h1);
    __nv_bfloat16 l0 = __float2bfloat16_rn(r0);
    __nv_bfloat16 l1 = __float2bfloat16_rn(r1);
    hi = (unsigned)__bfloat16_as_ushort(h0) | ((unsigned)__bfloat16_as_ushort(h1) << 16);
    lo = (unsigned)__bfloat16_as_ushort(l0) | ((unsigned)__bfloat16_as_ushort(l1) << 16);
}

__device__ __forceinline__ void mma16816(float (&c)[4], const unsigned (&a)[4],
                                         const unsigned b0, const unsigned b1) {
    asm volatile(
        "mma.sync.aligned.m16n8k16.row.col.f32.bf16.bf16.f32 "
        "{%0,%1,%2,%3}, {%4,%5,%6,%7}, {%8,%9}, {%0,%1,%2,%3};\n"
        : "+f"(c[0]), "+f"(c[1]), "+f"(c[2]), "+f"(c[3])
        : "r"(a[0]), "r"(a[1]), "r"(a[2]), "r"(a[3]), "r"(b0), "r"(b1));
}

// ---------------------------------------------------------------------------
// Conv3d 3x3x3 SAME + bias + tanh/sigmoid via implicit-GEMM HMMA (split bf16)
// Block: 256 thr (8 warps); tile 8h x 32w x 64co @ fixed (b,t).
// Warp wi owns output row h0+wi, 2 m-tiles (wseg 0/16), all 8 n-tiles.
// smem: fp32 halo [3tz][10y][34x][8ci pad 10] + weight frags for one cig.
// K-step s: tapA=2s (reg0/1), tapB=2s+1 (reg2/3), ci pair = (q*2, q*2+1).
// ---------------------------------------------------------------------------
#define SMX_WORDS 10200             /* 3*10*34*10 */
#define SWF_WORDS 14336             /* 14*2*8*32*2 */
#define CONV_SMEM (SMX_WORDS*4 + SWF_WORDS*4)

__global__ __launch_bounds__(256, 2)
void conv_kernel(const float* __restrict__ in, const float* __restrict__ bias) {
    extern __shared__ char smraw[];
    float*    s_x  = (float*)smraw;
    unsigned* s_wf = (unsigned*)(smraw + SMX_WORDS*4);

    const int w0 = blockIdx.x * 32;
    const int h0 = blockIdx.y * 8;
    const int bz = blockIdx.z;
    const int b  = bz / T_;
    const int t  = bz % T_;
    const int tid  = threadIdx.x;
    const int lane = tid & 31;
    const int wi   = tid >> 5;      // warp -> output row
    const int g2   = lane >> 2;     // groupID (row within m-tile)
    const int q2   = lane & 3;      // thread-in-group (k / n low bits)

    float acc[2][8][4];
    #pragma unroll
    for (int a2 = 0; a2 < 2; a2++)
        #pragma unroll
        for (int nt = 0; nt < 8; nt++)
            #pragma unroll
            for (int r = 0; r < 4; r++) acc[a2][nt][r] = 0.f;

    for (int cig = 0; cig < 4; cig++) {
        __syncthreads();
        // ---- fp32 halo load: [tz][y][x][ci] (ci stride pad 10) ----
        for (int li = tid; li < 8160; li += 256) {
            int x  = li % 34; int r2 = li / 34;
            int y  = r2 % 10; r2 /= 10;
            int tz = r2 % 3;  int ci8 = r2 / 3;
            int tt = t + tz - 1, gh = h0 + y - 1, gw = w0 + x - 1;
            float v = 0.f;
            if (tt >= 0 && tt < T_ && gh >= 0 && gh < H_ && gw >= 0 && gw < W_)
                v = in[((size_t)((b*CIN + cig*8 + ci8)*T_ + tt)*H_ + gh)*W_ + gw];
            s_x[((tz*10 + y)*34 + x)*10 + ci8] = v;
        }
        // ---- weight fragments for this cig ----
        {
            const uint4* src = (const uint4*)(g_wfrag + cig*SWF_WORDS);
            uint4* dst = (uint4*)s_wf;
            for (int li = tid; li < SWF_WORDS/4; li += 256) dst[li] = src[li];
        }
        __syncthreads();

        for (int s = 0; s < 14; s++) {
            const int tapA = 2*s, tapB = 2*s + 1;
            const int ktA = tapA/9, rA = tapA%9, khA = rA/3, kwA = rA%3;
            const bool zB = (tapB == 27);
            const int ktB = tapB/9, rB = tapB%9, khB = rB/3, kwB = rB%3;
            const int yA = wi + khA, yB = wi + khB;

            unsigned Ahi[2][4], Alo[2][4];
            #pragma unroll
            for (int a2 = 0; a2 < 2; a2++) {
                const int xb = a2*16 + g2;
                float2 v0 = *(const float2*)&s_x[((ktA*10 + yA)*34 + xb     + kwA)*10 + 2*q2];
                float2 v1 = *(const float2*)&s_x[((ktA*10 + yA)*34 + xb + 8 + kwA)*10 + 2*q2];
                float2 v2, v3;
                if (!zB) {
                    v2 = *(const float2*)&s_x[((ktB*10 + yB)*34 + xb     + kwB)*10 + 2*q2];
                    v3 = *(const float2*)&s_x[((ktB*10 + yB)*34 + xb + 8 + kwB)*10 + 2*q2];
                } else { v2 = make_float2(0.f,0.f); v3 = make_float2(0.f,0.f); }
                split_pack(v0.x, v0.y, Ahi[a2][0], Alo[a2][0]);
                split_pack(v1.x, v1.y, Ahi[a2][1], Alo[a2][1]);
                split_pack(v2.x, v2.y, Ahi[a2][2], Alo[a2][2]);
                split_pack(v3.x, v3.y, Ahi[a2][3], Alo[a2][3]);
            }
            // hi-weights: Ahi*Bhi + Alo*Bhi
            unsigned Bv[8][2];
            #pragma unroll
            for (int nt = 0; nt < 8; nt++) {
                const unsigned* p = &s_wf[((s*2 + 0)*8 + nt)*64 + lane*2];
                Bv[nt][0] = p[0]; Bv[nt][1] = p[1];
            }
            #pragma unroll
            for (int a2 = 0; a2 < 2; a2++)
                #pragma unroll
                for (int nt = 0; nt < 8; nt++) {
                    mma16816(acc[a2][nt], Ahi[a2], Bv[nt][0], Bv[nt][1]);
                    mma16816(acc[a2][nt], Alo[a2], Bv[nt][0], Bv[nt][1]);
                }
            // lo-weights: Ahi*Blo
            #pragma unroll
            for (int nt = 0; nt < 8; nt++) {
                const unsigned* p = &s_wf[((s*2 + 1)*8 + nt)*64 + lane*2];
                Bv[nt][0] = p[0]; Bv[nt][1] = p[1];
            }
            #pragma unroll
            for (int a2 = 0; a2 < 2; a2++)
                #pragma unroll
                for (int nt = 0; nt < 8; nt++)
                    mma16816(acc[a2][nt], Ahi[a2], Bv[nt][0], Bv[nt][1]);
        }
    }

    // ---- epilogue: bias + activation ----
    const int h = h0 + wi;
    #pragma unroll
    for (int a2 = 0; a2 < 2; a2++) {
        const int wbase = w0 + a2*16 + g2;
        #pragma unroll
        for (int nt = 0; nt < 8; nt++) {
            const int co = nt*8 + q2*2;
            const float b0v = __ldg(bias + co), b1v = __ldg(bias + co + 1);
            float x00 = acc[a2][nt][0] + b0v;   // row g   , co
            float x01 = acc[a2][nt][1] + b1v;   // row g   , co+1
            float x10 = acc[a2][nt][2] + b0v;   // row g+8 , co
            float x11 = acc[a2][nt][3] + b1v;   // row g+8 , co+1
            float y00, y01, y10, y11;
            float* dst; int c_;
            if (nt < 4) {
                y00 = tanhf(x00); y01 = tanhf(x01); y10 = tanhf(x10); y11 = tanhf(x11);
                dst = g_Z; c_ = co;
            } else {
                y00 = 1.f/(1.f + __expf(-x00)); y01 = 1.f/(1.f + __expf(-x01));
                y10 = 1.f/(1.f + __expf(-x10)); y11 = 1.f/(1.f + __expf(-x11));
                dst = g_F; c_ = co - HID;
            }
            size_t base0 = ((size_t)((b*HID + c_)*T_ + t)*H_ + h)*W_ + wbase;
            dst[base0]     = y00; dst[base0 + 8] = y10;
            size_t base1 = base0 + CTHW;
            dst[base1]     = y01; dst[base1 + 8] = y11;
        }
    }
}

// ---------------------------------------------------------------------------
// Fused recurrence + channel attention.
// Block: 256 thr, 16 pixels (b, h, w0..w0+15). smem h[16px][992] stride 993.
// Phase 1: h_t = f*h + (1-f)*z written straight into smem (no g_Hq).
// Phase 2: per warp 2 pixels; lane = channel row. Gram symmetry -> column
//          softmax stats come from own-row stats via 2 shuffles.
//          t-outer loops keep only a[32] live (in-place col-t overwrite safe).
// Phase 3: coalesced store to [B][C][T][H][W].
// ---------------------------------------------------------------------------
#define ATTN_SMEM (16*993*4)

__global__ __launch_bounds__(256, 3)
void attn_kernel(const float* __restrict__ gamma, float* __restrict__ out) {
    extern __shared__ float sq[];    // [16][993]
    const int w0 = blockIdx.x * 16;
    const int h  = blockIdx.y;
    const int b  = blockIdx.z;
    const int tid = threadIdx.x;

    // ---- phase 1: recurrence ----
    {
        const int px  = tid & 15;
        const int c16 = tid >> 4;
        #pragma unroll
        for (int ch = 0; ch < 2; ch++) {
            const int c = ch*16 + c16;
            size_t base = (size_t)((b*HID + c)*T_)*HW + (size_t)h*W_ + w0 + px;
            float hs = 0.f;
            float* dst = sq + px*993 + c*31;
            #pragma unroll
            for (int t = 0; t < T_; t++) {
                float z = g_Z[base + (size_t)t*HW];
                float f = g_F[base + (size_t)t*HW];
                hs = f*hs + (1.f - f)*z;
                dst[t] = hs;
            }
        }
    }
    __syncthreads();

    // ---- phase 2: attention ----
    const float gam = __ldg(gamma);
    const int lane = tid & 31;
    const int wid  = tid >> 5;

    for (int it = 0; it < 2; it++) {
        float* q = sq + (wid*2 + it)*993;
        float a[32];
        #pragma unroll
        for (int d = 0; d < 32; d++) a[d] = 0.f;

        #pragma unroll 1
        for (int t = 0; t < T_; t++) {
            float qt = q[lane*31 + t];
            #pragma unroll
            for (int d = 0; d < 32; d++) a[d] += qt * q[d*31 + t];
        }

        float m = a[0];
        #pragma unroll
        for (int d = 1; d < 32; d++) m = fmaxf(m, a[d]);
        float ssum = 0.f;
        #pragma unroll
        for (int d = 0; d < 32; d++) ssum += __expf(a[d] - m);

        #pragma unroll
        for (int d = 0; d < 32; d++) {
            float mc  = __shfl_sync(0xffffffffu, m,    d);
            float sc2 = __shfl_sync(0xffffffffu, ssum, d);
            a[d] = __expf(a[d] - mc) * (0.17677669529663687f / sc2); // /sqrt(32)
        }

        #pragma unroll 1
        for (int t = 0; t < T_; t++) {
            float acc2 = 0.f;
            #pragma unroll
            for (int d = 0; d < 32; d++) acc2 += a[d] * q[d*31 + t];
            float own = q[lane*31 + t];
            __syncwarp();
            q[lane*31 + t] = fmaf(gam, acc2, own);
            __syncwarp();
        }
    }
    __syncthreads();

    // ---- phase 3: coalesced store ----
    for (int i = tid; i < 16*992; i += 256) {
        int wpx = i & 15;
        int ct  = i >> 4;
        int c   = ct / 31;
        int t2  = ct - c*31;
        out[((size_t)((b*HID + c)*T_ + t2)*H_ + h)*W_ + w0 + wpx] =
            sq[wpx*993 + c*31 + t2];
    }
}

// ---------------------------------------------------------------------------
extern "C" void kernel_launch(void* const* d_in, const int* in_sizes, int n_in,
                              void* d_out, int out_size) {
    const float* input  = (const float*)d_in[0];
    const float* conv_w = (const float*)d_in[1];
    const float* conv_b = (const float*)d_in[2];
    const float* gamma  = (const float*)d_in[3];
    float* out = (float*)d_out;

    wfrag_kernel<<<(4*14336 + 255)/256, 256>>>(conv_w);

    cudaFuncSetAttribute(conv_kernel, cudaFuncAttributeMaxDynamicSharedMemorySize,
                         CONV_SMEM);
    dim3 cgrid(W_/32, H_/8, B_*T_);
    conv_kernel<<<cgrid, 256, CONV_SMEM>>>(input, conv_b);

    cudaFuncSetAttribute(attn_kernel, cudaFuncAttributeMaxDynamicSharedMemorySize,
                         ATTN_SMEM);
    dim3 agrid(W_/16, H_, B_);
    attn_kernel<<<agrid, 256, ATTN_SMEM>>>(gamma, out);
}

// round 3
// speedup vs baseline: 2.6473x; 1.2691x over previous
#include <cuda_runtime.h>
#include <cuda_bf16.h>
#include <math.h>

#define B_   4
#define CIN  32
#define HID  32
#define T_   31
#define H_   96
#define W_   96
#define HW   (H_*W_)          /* 9216 */
#define CTHW ((size_t)T_*HW)  /* per-channel stride 285696 */
#define NELEM (B_*HID*T_*HW)
#define NPIX  (B_*4*T_*H_*W_) /* b,cig,t,h,w = 4,571,136 */

// Scratch (device globals; no runtime allocation)
__device__ float g_Z[NELEM];              // tanh gate   [B][C][T][H][W]
__device__ float g_F[NELEM];              // sigmoid gate[B][C][T][H][W]
__device__ uint4 g_xh[NPIX];              // input bf16-hi, 8ci packed as 4 bf16x2
__device__ uint4 g_xl[NPIX];              // input bf16-lo residual
__device__ unsigned g_wfrag[4*14*2*8*32*2]; // weight fragments, HMMA B-order

// ---------------------------------------------------------------------------
// Input split prep: fp32 [b][ci][t][h][w] -> hi/lo bf16x2 uint4 [b][cig][t][h][w]
// word j of uint4 = (ci 2j in low16, ci 2j+1 in high16)
// ---------------------------------------------------------------------------
__global__ void xsplit_kernel(const float* __restrict__ in) {
    int idx = blockIdx.x * 256 + threadIdx.x;
    if (idx >= NPIX) return;
    int w = idx % W_; int r = idx / W_;
    int h = r % H_;   r /= H_;
    int t = r % T_;   r /= T_;
    int cig = r & 3;  int b = r >> 2;
    size_t base = ((size_t)((b*CIN + cig*8)*T_ + t)*H_ + h)*W_ + w;
    unsigned hiw[4], low[4];
    #pragma unroll
    for (int j = 0; j < 4; j++) {
        float f0 = in[base + (size_t)(2*j)*CTHW];
        float f1 = in[base + (size_t)(2*j+1)*CTHW];
        __nv_bfloat16 h0 = __float2bfloat16_rn(f0);
        __nv_bfloat16 h1 = __float2bfloat16_rn(f1);
        __nv_bfloat16 l0 = __float2bfloat16_rn(f0 - __bfloat162float(h0));
        __nv_bfloat16 l1 = __float2bfloat16_rn(f1 - __bfloat162float(h1));
        hiw[j] = (unsigned)__bfloat16_as_ushort(h0) | ((unsigned)__bfloat16_as_ushort(h1) << 16);
        low[j] = (unsigned)__bfloat16_as_ushort(l0) | ((unsigned)__bfloat16_as_ushort(l1) << 16);
    }
    g_xh[idx] = make_uint4(hiw[0], hiw[1], hiw[2], hiw[3]);
    g_xl[idx] = make_uint4(low[0], low[1], low[2], low[3]);
}

// ---------------------------------------------------------------------------
// Weight fragment prep: conv_w [co=64][ci=32][tap=27] -> bf16 hi/lo fragments
// k = tap*8 + ci_local (tap padded to 28; tap 27 == zero)
// word idx = cig*14336 + s*1024 + split*512 + nt*64 + lane*2 + r
// ---------------------------------------------------------------------------
__global__ void wfrag_kernel(const float* __restrict__ w) {
    int idx = blockIdx.x * 256 + threadIdx.x;
    if (idx >= 4*14336) return;
    int r    = idx & 1;
    int lane = (idx >> 1) & 31;
    int nt   = (idx >> 6) & 7;
    int split= (idx >> 9) & 1;
    int rest = idx >> 10;
    int s    = rest % 14;
    int cig  = rest / 14;
    int q    = lane & 3;
    int n    = nt*8 + (lane >> 2);     // co
    unsigned word = 0;
    for (int e = 0; e < 2; e++) {
        int k   = s*16 + q*2 + r*8 + e;
        int cil = k & 7;
        int tap = k >> 3;
        float val = 0.f;
        if (tap < 27) val = w[(n*CIN + (cig*8 + cil))*27 + tap];
        __nv_bfloat16 hb = __float2bfloat16_rn(val);
        __nv_bfloat16 res = hb;
        if (split) res = __float2bfloat16_rn(val - __bfloat162float(hb));
        word |= ((unsigned)__bfloat16_as_ushort(res)) << (16*e);
    }
    g_wfrag[idx] = word;
}

// tiny no-op; used to align the ncu -s 5 capture window onto conv_kernel
__global__ void noop_kernel() {}

// ---------------------------------------------------------------------------
__device__ __forceinline__ void mma16816(float (&c)[4], const unsigned (&a)[4],
                                         const unsigned b0, const unsigned b1) {
    asm volatile(
        "mma.sync.aligned.m16n8k16.row.col.f32.bf16.bf16.f32 "
        "{%0,%1,%2,%3}, {%4,%5,%6,%7}, {%8,%9}, {%0,%1,%2,%3};\n"
        : "+f"(c[0]), "+f"(c[1]), "+f"(c[2]), "+f"(c[3])
        : "r"(a[0]), "r"(a[1]), "r"(a[2]), "r"(a[3]), "r"(b0), "r"(b1));
}

// ---------------------------------------------------------------------------
// Conv3d 3x3x3 SAME + bias + tanh/sigmoid via implicit-GEMM HMMA (split bf16)
// Block: 256 thr (8 warps); tile 8h x 32w x 64co @ fixed (b,t).
// smem: pre-split halo hi/lo [3tz][10y][34x][4 words] + weight frags for one cig.
// A-fragment = bare LDS.32 (warp spans one contiguous 128B run: conflict-free).
// ---------------------------------------------------------------------------
#define SXA_WORDS (3*10*34*4)       /* 4080 words per array */
#define SWF_WORDS 14336             /* 14*2*8*32*2 */
#define CONV_SMEM ((2*SXA_WORDS + SWF_WORDS)*4)

__global__ __launch_bounds__(256, 2)
void conv_kernel(const float* __restrict__ bias) {
    extern __shared__ unsigned smw[];
    unsigned* s_xh = smw;
    unsigned* s_xl = smw + SXA_WORDS;
    unsigned* s_wf = smw + 2*SXA_WORDS;

    const int w0 = blockIdx.x * 32;
    const int h0 = blockIdx.y * 8;
    const int bz = blockIdx.z;
    const int b  = bz / T_;
    const int t  = bz % T_;
    const int tid  = threadIdx.x;
    const int lane = tid & 31;
    const int wi   = tid >> 5;      // warp -> output row
    const int g2   = lane >> 2;     // m-row within tile
    const int q2   = lane & 3;      // k / n low bits

    float acc[2][8][4];
    #pragma unroll
    for (int a2 = 0; a2 < 2; a2++)
        #pragma unroll
        for (int nt = 0; nt < 8; nt++)
            #pragma unroll
            for (int r = 0; r < 4; r++) acc[a2][nt][r] = 0.f;

    for (int cig = 0; cig < 4; cig++) {
        __syncthreads();
        // ---- halo load: pure uint4 copy of pre-split input ----
        for (int li = tid; li < 2040; li += 256) {
            int which = (li >= 1020);
            int e = li - which*1020;
            int x  = e % 34; int r2 = e / 34;
            int y  = r2 % 10; int tz = r2 / 10;
            int tt = t + tz - 1, gh = h0 + y - 1, gw = w0 + x - 1;
            uint4 v = make_uint4(0u,0u,0u,0u);
            if (tt >= 0 && tt < T_ && gh >= 0 && gh < H_ && gw >= 0 && gw < W_) {
                size_t gi = ((size_t)((b*4 + cig)*T_ + tt)*H_ + gh)*W_ + gw;
                v = which ? g_xl[gi] : g_xh[gi];
            }
            unsigned* dst = (which ? s_xl : s_xh) + e*4;
            *(uint4*)dst = v;
        }
        // ---- weight fragments for this cig ----
        {
            const uint4* src = (const uint4*)(g_wfrag + cig*SWF_WORDS);
            uint4* dst = (uint4*)s_wf;
            for (int li = tid; li < SWF_WORDS/4; li += 256) dst[li] = src[li];
        }
        __syncthreads();

        #pragma unroll
        for (int s = 0; s < 14; s++) {
            const int tapA = 2*s, tapB = 2*s + 1;
            const int ktA = tapA/9, rA = tapA%9, khA = rA/3, kwA = rA%3;
            const bool zB = (tapB == 27);
            const int ktB = zB ? 0 : tapB/9;
            const int rB  = zB ? 0 : tapB%9;
            const int khB = rB/3, kwB = rB%3;
            const int yA = wi + khA, yB = wi + khB;

            unsigned Ahi[2][4], Alo[2][4];
            #pragma unroll
            for (int a2 = 0; a2 < 2; a2++) {
                const int xb = a2*16 + g2;
                const int iA0 = ((ktA*10 + yA)*34 + xb + kwA)*4 + q2;
                Ahi[a2][0] = s_xh[iA0];       Alo[a2][0] = s_xl[iA0];
                Ahi[a2][1] = s_xh[iA0 + 32];  Alo[a2][1] = s_xl[iA0 + 32];
                if (!zB) {
                    const int iB0 = ((ktB*10 + yB)*34 + xb + kwB)*4 + q2;
                    Ahi[a2][2] = s_xh[iB0];       Alo[a2][2] = s_xl[iB0];
                    Ahi[a2][3] = s_xh[iB0 + 32];  Alo[a2][3] = s_xl[iB0 + 32];
                } else {
                    Ahi[a2][2] = 0u; Ahi[a2][3] = 0u;
                    Alo[a2][2] = 0u; Alo[a2][3] = 0u;
                }
            }
            unsigned Bv[8][2];
            #pragma unroll
            for (int nt = 0; nt < 8; nt++) {
                const unsigned* p = &s_wf[((s*2 + 0)*8 + nt)*64 + lane*2];
                Bv[nt][0] = p[0]; Bv[nt][1] = p[1];
            }
            #pragma unroll
            for (int a2 = 0; a2 < 2; a2++)
                #pragma unroll
                for (int nt = 0; nt < 8; nt++) {
                    mma16816(acc[a2][nt], Ahi[a2], Bv[nt][0], Bv[nt][1]);
                    mma16816(acc[a2][nt], Alo[a2], Bv[nt][0], Bv[nt][1]);
                }
            #pragma unroll
            for (int nt = 0; nt < 8; nt++) {
                const unsigned* p = &s_wf[((s*2 + 1)*8 + nt)*64 + lane*2];
                Bv[nt][0] = p[0]; Bv[nt][1] = p[1];
            }
            #pragma unroll
            for (int a2 = 0; a2 < 2; a2++)
                #pragma unroll
                for (int nt = 0; nt < 8; nt++)
                    mma16816(acc[a2][nt], Ahi[a2], Bv[nt][0], Bv[nt][1]);
        }
    }

    // ---- epilogue: bias + activation ----
    const int h = h0 + wi;
    #pragma unroll
    for (int a2 = 0; a2 < 2; a2++) {
        const int wbase = w0 + a2*16 + g2;
        #pragma unroll
        for (int nt = 0; nt < 8; nt++) {
            const int co = nt*8 + q2*2;
            const float b0v = __ldg(bias + co), b1v = __ldg(bias + co + 1);
            float x00 = acc[a2][nt][0] + b0v;
            float x01 = acc[a2][nt][1] + b1v;
            float x10 = acc[a2][nt][2] + b0v;
            float x11 = acc[a2][nt][3] + b1v;
            float y00, y01, y10, y11;
            float* dst; int c_;
            if (nt < 4) {
                y00 = tanhf(x00); y01 = tanhf(x01); y10 = tanhf(x10); y11 = tanhf(x11);
                dst = g_Z; c_ = co;
            } else {
                y00 = 1.f/(1.f + __expf(-x00)); y01 = 1.f/(1.f + __expf(-x01));
                y10 = 1.f/(1.f + __expf(-x10)); y11 = 1.f/(1.f + __expf(-x11));
                dst = g_F; c_ = co - HID;
            }
            size_t base0 = ((size_t)((b*HID + c_)*T_ + t)*H_ + h)*W_ + wbase;
            dst[base0]     = y00; dst[base0 + 8] = y10;
            size_t base1 = base0 + CTHW;
            dst[base1]     = y01; dst[base1 + 8] = y11;
        }
    }
}

// ---------------------------------------------------------------------------
// Fused recurrence + channel attention (unchanged from R2).
// ---------------------------------------------------------------------------
#define ATTN_SMEM (16*993*4)

__global__ __launch_bounds__(256, 3)
void attn_kernel(const float* __restrict__ gamma, float* __restrict__ out) {
    extern __shared__ float sq[];    // [16][993]
    const int w0 = blockIdx.x * 16;
    const int h  = blockIdx.y;
    const int b  = blockIdx.z;
    const int tid = threadIdx.x;

    // ---- phase 1: recurrence ----
    {
        const int px  = tid & 15;
        const int c16 = tid >> 4;
        #pragma unroll
        for (int ch = 0; ch < 2; ch++) {
            const int c = ch*16 + c16;
            size_t base = (size_t)((b*HID + c)*T_)*HW + (size_t)h*W_ + w0 + px;
            float hs = 0.f;
            float* dst = sq + px*993 + c*31;
            #pragma unroll
            for (int t = 0; t < T_; t++) {
                float z = g_Z[base + (size_t)t*HW];
                float f = g_F[base + (size_t)t*HW];
                hs = f*hs + (1.f - f)*z;
                dst[t] = hs;
            }
        }
    }
    __syncthreads();

    // ---- phase 2: attention ----
    const float gam = __ldg(gamma);
    const int lane = tid & 31;
    const int wid  = tid >> 5;

    for (int it = 0; it < 2; it++) {
        float* q = sq + (wid*2 + it)*993;
        float a[32];
        #pragma unroll
        for (int d = 0; d < 32; d++) a[d] = 0.f;

        #pragma unroll 1
        for (int t = 0; t < T_; t++) {
            float qt = q[lane*31 + t];
            #pragma unroll
            for (int d = 0; d < 32; d++) a[d] += qt * q[d*31 + t];
        }

        float m = a[0];
        #pragma unroll
        for (int d = 1; d < 32; d++) m = fmaxf(m, a[d]);
        float ssum = 0.f;
        #pragma unroll
        for (int d = 0; d < 32; d++) ssum += __expf(a[d] - m);

        #pragma unroll
        for (int d = 0; d < 32; d++) {
            float mc  = __shfl_sync(0xffffffffu, m,    d);
            float sc2 = __shfl_sync(0xffffffffu, ssum, d);
            a[d] = __expf(a[d] - mc) * (0.17677669529663687f / sc2); // /sqrt(32)
        }

        #pragma unroll 1
        for (int t = 0; t < T_; t++) {
            float acc2 = 0.f;
            #pragma unroll
            for (int d = 0; d < 32; d++) acc2 += a[d] * q[d*31 + t];
            float own = q[lane*31 + t];
            __syncwarp();
            q[lane*31 + t] = fmaf(gam, acc2, own);
            __syncwarp();
        }
    }
    __syncthreads();

    // ---- phase 3: coalesced store ----
    for (int i = tid; i < 16*992; i += 256) {
        int wpx = i & 15;
        int ct  = i >> 4;
        int c   = ct / 31;
        int t2  = ct - c*31;
        out[((size_t)((b*HID + c)*T_ + t2)*H_ + h)*W_ + w0 + wpx] =
            sq[wpx*993 + c*31 + t2];
    }
}

// ---------------------------------------------------------------------------
extern "C" void kernel_launch(void* const* d_in, const int* in_sizes, int n_in,
                              void* d_out, int out_size) {
    const float* input  = (const float*)d_in[0];
    const float* conv_w = (const float*)d_in[1];
    const float* conv_b = (const float*)d_in[2];
    const float* gamma  = (const float*)d_in[3];
    float* out = (float*)d_out;

    xsplit_kernel<<<(NPIX + 255)/256, 256>>>(input);           // launch 0
    wfrag_kernel<<<(4*14336 + 255)/256, 256>>>(conv_w);        // launch 1
    noop_kernel<<<1, 32>>>();                                  // launch 2
    noop_kernel<<<1, 32>>>();                                  // launch 3
    noop_kernel<<<1, 32>>>();                                  // launch 4

    cudaFuncSetAttribute(conv_kernel, cudaFuncAttributeMaxDynamicSharedMemorySize,
                         CONV_SMEM);
    dim3 cgrid(W_/32, H_/8, B_*T_);
    conv_kernel<<<cgrid, 256, CONV_SMEM>>>(conv_b);            // launch 5 -> ncu

    cudaFuncSetAttribute(attn_kernel, cudaFuncAttributeMaxDynamicSharedMemorySize,
                         ATTN_SMEM);
    dim3 agrid(W_/16, H_, B_);
    attn_kernel<<<agrid, 256, ATTN_SMEM>>>(gamma, out);        // launch 6
}

// round 5
// speedup vs baseline: 2.7318x; 1.0319x over previous
#include <cuda_runtime.h>
#include <cuda_bf16.h>
#include <math.h>

#define B_   4
#define CIN  32
#define HID  32
#define T_   31
#define H_   96
#define W_   96
#define HW   (H_*W_)          /* 9216 */
#define CTHW ((size_t)T_*HW)  /* per-channel stride 285696 */
#define NELEM (B_*HID*T_*HW)
#define NPIX  (B_*4*T_*H_*W_) /* b,cig,t,h,w = 4,571,136 */

// Scratch (device globals; no runtime allocation)
__device__ float g_Z[NELEM];                // tanh gate   [B][C][T][H][W]
__device__ float g_F[NELEM];                // sigmoid gate[B][C][T][H][W]
__device__ uint4 g_x[NPIX*2];               // input bf16 hi/lo interleaved
__device__ unsigned g_wfrag[4*14*8*32*4];   // weight fragments, hi/lo interleaved

// ---------------------------------------------------------------------------
// f32x2 packed-FMA helpers (Blackwell)
// ---------------------------------------------------------------------------
__device__ __forceinline__ unsigned long long ffma2(unsigned long long a,
                                                    unsigned long long b,
                                                    unsigned long long c) {
    unsigned long long d;
    asm("fma.rn.f32x2 %0, %1, %2, %3;" : "=l"(d) : "l"(a), "l"(b), "l"(c));
    return d;
}
__device__ __forceinline__ unsigned long long pack2(float lo, float hi) {
    unsigned long long r;
    asm("mov.b64 %0, {%1, %2};" : "=l"(r) : "f"(lo), "f"(hi));
    return r;
}
__device__ __forceinline__ void unpack2(unsigned long long v, float &lo, float &hi) {
    asm("mov.b64 {%0, %1}, %2;" : "=f"(lo), "=f"(hi) : "l"(v));
}

// ---------------------------------------------------------------------------
// Input split prep: fp32 -> interleaved hi/lo bf16x2.
// Pixel word order: hi01, lo01, hi23, lo23 | hi45, lo45, hi67, lo67
// ---------------------------------------------------------------------------
__global__ void xsplit_kernel(const float* __restrict__ in) {
    int idx = blockIdx.x * 256 + threadIdx.x;
    if (idx >= NPIX) return;
    int w = idx % W_; int r = idx / W_;
    int h = r % H_;   r /= H_;
    int t = r % T_;   r /= T_;
    int cig = r & 3;  int b = r >> 2;
    size_t base = ((size_t)((b*CIN + cig*8)*T_ + t)*H_ + h)*W_ + w;
    unsigned hiw[4], low[4];
    #pragma unroll
    for (int j = 0; j < 4; j++) {
        float f0 = in[base + (size_t)(2*j)*CTHW];
        float f1 = in[base + (size_t)(2*j+1)*CTHW];
        __nv_bfloat16 h0 = __float2bfloat16_rn(f0);
        __nv_bfloat16 h1 = __float2bfloat16_rn(f1);
        __nv_bfloat16 l0 = __float2bfloat16_rn(f0 - __bfloat162float(h0));
        __nv_bfloat16 l1 = __float2bfloat16_rn(f1 - __bfloat162float(h1));
        hiw[j] = (unsigned)__bfloat16_as_ushort(h0) | ((unsigned)__bfloat16_as_ushort(h1) << 16);
        low[j] = (unsigned)__bfloat16_as_ushort(l0) | ((unsigned)__bfloat16_as_ushort(l1) << 16);
    }
    g_x[idx*2]   = make_uint4(hiw[0], low[0], hiw[1], low[1]);
    g_x[idx*2+1] = make_uint4(hiw[2], low[2], hiw[3], low[3]);
}

// ---------------------------------------------------------------------------
// Weight fragment prep. word idx = cig*14336 + s*1024 + nt*128 + lane*4 + j
// j: 0=hi r0, 1=hi r1, 2=lo r0, 3=lo r1  (one LDS.128 per (s,nt,lane))
// k = tap*8 + ci_local (tap padded to 28; tap 27 == zero)
// ---------------------------------------------------------------------------
__global__ void wfrag_kernel(const float* __restrict__ w) {
    int idx = blockIdx.x * 256 + threadIdx.x;
    if (idx >= 4*14336) return;
    int j    = idx & 3;
    int lane = (idx >> 2) & 31;
    int nt   = (idx >> 7) & 7;
    int rest = idx >> 10;
    int s    = rest % 14;
    int cig  = rest / 14;
    int r     = j & 1;
    int split = j >> 1;
    int q = lane & 3;
    int n = nt*8 + (lane >> 2);     // co
    unsigned word = 0;
    for (int e = 0; e < 2; e++) {
        int k   = s*16 + q*2 + r*8 + e;
        int cil = k & 7;
        int tap = k >> 3;
        float val = 0.f;
        if (tap < 27) val = w[(n*CIN + (cig*8 + cil))*27 + tap];
        __nv_bfloat16 hb = __float2bfloat16_rn(val);
        __nv_bfloat16 res = hb;
        if (split) res = __float2bfloat16_rn(val - __bfloat162float(hb));
        word |= ((unsigned)__bfloat16_as_ushort(res)) << (16*e);
    }
    g_wfrag[idx] = word;
}

// aligns the profiled launch (harness+2, skip 5 => our index 3) onto conv
__global__ void noop_kernel() {}

// ---------------------------------------------------------------------------
__device__ __forceinline__ void mma16816(float (&c)[4], const unsigned (&a)[4],
                                         const unsigned b0, const unsigned b1) {
    asm volatile(
        "mma.sync.aligned.m16n8k16.row.col.f32.bf16.bf16.f32 "
        "{%0,%1,%2,%3}, {%4,%5,%6,%7}, {%8,%9}, {%0,%1,%2,%3};\n"
        : "+f"(c[0]), "+f"(c[1]), "+f"(c[2]), "+f"(c[3])
        : "r"(a[0]), "r"(a[1]), "r"(a[2]), "r"(a[3]), "r"(b0), "r"(b1));
}

// ---------------------------------------------------------------------------
// Conv3d 3x3x3 SAME + bias + tanh/sigmoid via implicit-GEMM HMMA (split bf16)
// smem: interleaved hi/lo halo [3tz][10y][34x][8 words] + weight frags (1 cig).
// A fragment pair = 1 LDS.64; B fragment group = 1 LDS.128 per nt (streamed).
// Pixel stride in smem = 8 words; +8 pixels = +64 words.
// ---------------------------------------------------------------------------
#define SX_WORDS (3*10*34*8)        /* 8160 words */
#define SWF_WORDS 14336
#define CONV_SMEM ((SX_WORDS + SWF_WORDS)*4)

__global__ __launch_bounds__(256, 2)
void conv_kernel(const float* __restrict__ bias) {
    extern __shared__ unsigned smw[];
    unsigned* s_x  = smw;
    unsigned* s_wf = smw + SX_WORDS;

    const int w0 = blockIdx.x * 32;
    const int h0 = blockIdx.y * 8;
    const int bz = blockIdx.z;
    const int b  = bz / T_;
    const int t  = bz % T_;
    const int tid  = threadIdx.x;
    const int lane = tid & 31;
    const int wi   = tid >> 5;      // warp -> output row
    const int g2   = lane >> 2;     // m-row within tile
    const int q2   = lane & 3;      // k / n low bits

    float acc[2][8][4];
    #pragma unroll
    for (int a2 = 0; a2 < 2; a2++)
        #pragma unroll
        for (int nt = 0; nt < 8; nt++)
            #pragma unroll
            for (int r = 0; r < 4; r++) acc[a2][nt][r] = 0.f;

    for (int cig = 0; cig < 4; cig++) {
        __syncthreads();
        // ---- halo load: uint4 copy of pre-split interleaved input ----
        for (int li = tid; li < 2040; li += 256) {
            int half = li & 1;
            int e    = li >> 1;
            int x  = e % 34; int r2 = e / 34;
            int y  = r2 % 10; int tz = r2 / 10;
            int tt = t + tz - 1, gh = h0 + y - 1, gw = w0 + x - 1;
            uint4 v = make_uint4(0u,0u,0u,0u);
            if (tt >= 0 && tt < T_ && gh >= 0 && gh < H_ && gw >= 0 && gw < W_) {
                size_t gi = ((size_t)((b*4 + cig)*T_ + tt)*H_ + gh)*W_ + gw;
                v = g_x[gi*2 + half];
            }
            *(uint4*)(s_x + e*8 + half*4) = v;
        }
        // ---- weight fragments for this cig ----
        {
            const uint4* src = (const uint4*)(g_wfrag + cig*SWF_WORDS);
            uint4* dst = (uint4*)s_wf;
            for (int li = tid; li < SWF_WORDS/4; li += 256) dst[li] = src[li];
        }
        __syncthreads();

        #pragma unroll
        for (int s = 0; s < 14; s++) {
            const int tapA = 2*s, tapB = 2*s + 1;
            const int ktA = tapA/9, rA = tapA%9, khA = rA/3, kwA = rA%3;
            const bool zB = (tapB == 27);
            const int ktB = zB ? 0 : tapB/9;
            const int rB  = zB ? 0 : tapB%9;
            const int khB = rB/3, kwB = rB%3;
            const int yA = wi + khA, yB = wi + khB;

            unsigned Ahi[2][4], Alo[2][4];
            #pragma unroll
            for (int a2 = 0; a2 < 2; a2++) {
                const int xb = a2*16 + g2;
                const int iA0 = (((ktA*10 + yA)*34 + xb + kwA)*8) + q2*2;
                uint2 p0 = *(const uint2*)(s_x + iA0);
                uint2 p1 = *(const uint2*)(s_x + iA0 + 64);    /* +8 pixels */
                Ahi[a2][0] = p0.x; Alo[a2][0] = p0.y;
                Ahi[a2][1] = p1.x; Alo[a2][1] = p1.y;
                if (!zB) {
                    const int iB0 = (((ktB*10 + yB)*34 + xb + kwB)*8) + q2*2;
                    uint2 p2 = *(const uint2*)(s_x + iB0);
                    uint2 p3 = *(const uint2*)(s_x + iB0 + 64); /* +8 pixels */
                    Ahi[a2][2] = p2.x; Alo[a2][2] = p2.y;
                    Ahi[a2][3] = p3.x; Alo[a2][3] = p3.y;
                } else {
                    Ahi[a2][2] = 0u; Ahi[a2][3] = 0u;
                    Alo[a2][2] = 0u; Alo[a2][3] = 0u;
                }
            }
            #pragma unroll
            for (int nt = 0; nt < 8; nt++) {
                uint4 B4 = *(const uint4*)(s_wf + (s*8 + nt)*128 + lane*4);
                mma16816(acc[0][nt], Ahi[0], B4.x, B4.y);
                mma16816(acc[1][nt], Ahi[1], B4.x, B4.y);
                mma16816(acc[0][nt], Alo[0], B4.x, B4.y);
                mma16816(acc[1][nt], Alo[1], B4.x, B4.y);
                mma16816(acc[0][nt], Ahi[0], B4.z, B4.w);
                mma16816(acc[1][nt], Ahi[1], B4.z, B4.w);
            }
        }
    }

    // ---- epilogue: bias + activation ----
    const int h = h0 + wi;
    #pragma unroll
    for (int a2 = 0; a2 < 2; a2++) {
        const int wbase = w0 + a2*16 + g2;
        #pragma unroll
        for (int nt = 0; nt < 8; nt++) {
            const int co = nt*8 + q2*2;
            const float b0v = __ldg(bias + co), b1v = __ldg(bias + co + 1);
            float x00 = acc[a2][nt][0] + b0v;
            float x01 = acc[a2][nt][1] + b1v;
            float x10 = acc[a2][nt][2] + b0v;
            float x11 = acc[a2][nt][3] + b1v;
            float y00, y01, y10, y11;
            float* dst; int c_;
            if (nt < 4) {
                y00 = tanhf(x00); y01 = tanhf(x01); y10 = tanhf(x10); y11 = tanhf(x11);
                dst = g_Z; c_ = co;
            } else {
                y00 = 1.f/(1.f + __expf(-x00)); y01 = 1.f/(1.f + __expf(-x01));
                y10 = 1.f/(1.f + __expf(-x10)); y11 = 1.f/(1.f + __expf(-x11));
                dst = g_F; c_ = co - HID;
            }
            size_t base0 = ((size_t)((b*HID + c_)*T_ + t)*H_ + h)*W_ + wbase;
            dst[base0]     = y00; dst[base0 + 8] = y10;
            size_t base1 = base0 + CTHW;
            dst[base1]     = y01; dst[base1 + 8] = y11;
        }
    }
}

// ---------------------------------------------------------------------------
// Fused recurrence + channel attention, f32x2 edition.
// 16 pixels/block; row stride 34 (t=31 slot zeroed), pixel stride 1090.
// ---------------------------------------------------------------------------
#define RS   34
#define PS   1090
#define ATTN_SMEM (16*PS*4)

__global__ __launch_bounds__(256, 2)
void attn_kernel(const float* __restrict__ gamma, float* __restrict__ out) {
    extern __shared__ float sq[];    // [16][1090]
    const int w0 = blockIdx.x * 16;
    const int h  = blockIdx.y;
    const int b  = blockIdx.z;
    const int tid = threadIdx.x;

    // ---- phase 1: recurrence ----
    {
        const int px  = tid & 15;
        const int c16 = tid >> 4;
        #pragma unroll
        for (int ch = 0; ch < 2; ch++) {
            const int c = ch*16 + c16;
            size_t base = (size_t)((b*HID + c)*T_)*HW + (size_t)h*W_ + w0 + px;
            float hs = 0.f;
            float* dst = sq + px*PS + c*RS;
            #pragma unroll
            for (int t = 0; t < T_; t++) {
                float z = g_Z[base + (size_t)t*HW];
                float f = g_F[base + (size_t)t*HW];
                hs = f*hs + (1.f - f)*z;
                dst[t] = hs;
            }
            dst[31] = 0.f;   // pad slot read by float2 pair (30,31)
        }
    }
    __syncthreads();

    // ---- phase 2: attention ----
    const float gam = __ldg(gamma);
    const int lane = tid & 31;
    const int wid  = tid >> 5;

    for (int it = 0; it < 2; it++) {
        float* q = sq + (wid*2 + it)*PS;

        unsigned long long qrp[16];
        #pragma unroll
        for (int tp = 0; tp < 16; tp++)
            qrp[tp] = *(const unsigned long long*)&q[lane*RS + 2*tp];

        float a[32];
        #pragma unroll 4
        for (int d = 0; d < 32; d++) {
            const float* row = q + d*RS;
            unsigned long long acc2 = 0ULL;
            #pragma unroll
            for (int tp = 0; tp < 16; tp++)
                acc2 = ffma2(*(const unsigned long long*)&row[2*tp], qrp[tp], acc2);
            float lo, hi; unpack2(acc2, lo, hi);
            a[d] = lo + hi;
        }

        float m = a[0];
        #pragma unroll
        for (int d = 1; d < 32; d++) m = fmaxf(m, a[d]);
        float ssum = 0.f;
        #pragma unroll
        for (int d = 0; d < 32; d++) ssum += __expf(a[d] - m);

        #pragma unroll
        for (int d = 0; d < 32; d++) {
            float mc  = __shfl_sync(0xffffffffu, m,    d);
            float sc2 = __shfl_sync(0xffffffffu, ssum, d);
            a[d] = __expf(a[d] - mc) * (0.17677669529663687f / sc2); // /sqrt(32)
        }

        unsigned long long ahp[16];
        #pragma unroll
        for (int tp = 0; tp < 16; tp++) ahp[tp] = 0ULL;
        #pragma unroll 4
        for (int d = 0; d < 32; d++) {
            unsigned long long ad2 = pack2(a[d], a[d]);
            const float* row = q + d*RS;
            #pragma unroll
            for (int tp = 0; tp < 16; tp++)
                ahp[tp] = ffma2(*(const unsigned long long*)&row[2*tp], ad2, ahp[tp]);
        }

        __syncwarp();
        #pragma unroll
        for (int tp = 0; tp < 16; tp++) {
            float lo, hi; unpack2(ahp[tp], lo, hi);
            float2 own = *(float2*)&q[lane*RS + 2*tp];
            own.x = fmaf(gam, lo, own.x);
            own.y = fmaf(gam, hi, own.y);
            *(float2*)&q[lane*RS + 2*tp] = own;   // slot 31 garbage, never read
        }
        __syncwarp();
    }
    __syncthreads();

    // ---- phase 3: coalesced store to [B][C][T][H][W] ----
    for (int i = tid; i < 16*992; i += 256) {
        int wpx = i & 15;
        int ct  = i >> 4;
        int c   = ct / 31;
        int t2  = ct - c*31;
        out[((size_t)((b*HID + c)*T_ + t2)*H_ + h)*W_ + w0 + wpx] =
            sq[wpx*PS + c*RS + t2];
    }
}

// ---------------------------------------------------------------------------
extern "C" void kernel_launch(void* const* d_in, const int* in_sizes, int n_in,
                              void* d_out, int out_size) {
    const float* input  = (const float*)d_in[0];
    const float* conv_w = (const float*)d_in[1];
    const float* conv_b = (const float*)d_in[2];
    const float* gamma  = (const float*)d_in[3];
    float* out = (float*)d_out;

    xsplit_kernel<<<(NPIX + 255)/256, 256>>>(input);           // our idx 0
    wfrag_kernel<<<(4*14336 + 255)/256, 256>>>(conv_w);        // our idx 1
    noop_kernel<<<1, 32>>>();                                  // our idx 2

    cudaFuncSetAttribute(conv_kernel, cudaFuncAttributeMaxDynamicSharedMemorySize,
                         CONV_SMEM);
    dim3 cgrid(W_/32, H_/8, B_*T_);
    conv_kernel<<<cgrid, 256, CONV_SMEM>>>(conv_b);            // our idx 3 -> ncu

    cudaFuncSetAttribute(attn_kernel, cudaFuncAttributeMaxDynamicSharedMemorySize,
                         ATTN_SMEM);
    dim3 agrid(W_/16, H_, B_);
    attn_kernel<<<agrid, 256, ATTN_SMEM>>>(gamma, out);        // our idx 4
}

// round 6
// speedup vs baseline: 5.4311x; 1.9881x over previous
#include <cuda_runtime.h>
#include <cuda_fp16.h>
#include <math.h>

#define B_   4
#define CIN  32
#define HID  32
#define T_   31
#define H_   96
#define W_   96
#define HW   (H_*W_)          /* 9216 */
#define CTHW ((size_t)T_*HW)  /* per-channel stride 285696 */
#define NELEM (B_*HID*T_*HW)
#define NPIX  (B_*4*T_*H_*W_) /* b,cig,t,h,w = 4,571,136 */

// Scratch (device globals; no runtime allocation)
__device__ float g_Z[NELEM];                // tanh gate   [B][C][T][H][W]
__device__ float g_F[NELEM];                // sigmoid gate[B][C][T][H][W]
__device__ uint4 g_x[NPIX];                 // input fp16: pixel = 8 ci (4 fp16x2)
__device__ unsigned g_wfrag[4*14*4*32*4];   // fp16 weight fragments (2 nt / uint4)

// ---------------------------------------------------------------------------
// f32x2 packed-FMA helpers (Blackwell)
// ---------------------------------------------------------------------------
__device__ __forceinline__ unsigned long long ffma2(unsigned long long a,
                                                    unsigned long long b,
                                                    unsigned long long c) {
    unsigned long long d;
    asm("fma.rn.f32x2 %0, %1, %2, %3;" : "=l"(d) : "l"(a), "l"(b), "l"(c));
    return d;
}
__device__ __forceinline__ unsigned long long pack2(float lo, float hi) {
    unsigned long long r;
    asm("mov.b64 %0, {%1, %2};" : "=l"(r) : "f"(lo), "f"(hi));
    return r;
}
__device__ __forceinline__ void unpack2(unsigned long long v, float &lo, float &hi) {
    asm("mov.b64 {%0, %1}, %2;" : "=f"(lo), "=f"(hi) : "l"(v));
}

// ---------------------------------------------------------------------------
// Input prep: fp32 -> fp16x2, pixel = 8 ci packed into one uint4.
// word j = (ci 2j in low16, ci 2j+1 in high16)
// ---------------------------------------------------------------------------
__global__ void xsplit_kernel(const float* __restrict__ in) {
    int idx = blockIdx.x * 256 + threadIdx.x;
    if (idx >= NPIX) return;
    int w = idx % W_; int r = idx / W_;
    int h = r % H_;   r /= H_;
    int t = r % T_;   r /= T_;
    int cig = r & 3;  int b = r >> 2;
    size_t base = ((size_t)((b*CIN + cig*8)*T_ + t)*H_ + h)*W_ + w;
    unsigned wds[4];
    #pragma unroll
    for (int j = 0; j < 4; j++) {
        __half h0 = __float2half_rn(in[base + (size_t)(2*j)*CTHW]);
        __half h1 = __float2half_rn(in[base + (size_t)(2*j+1)*CTHW]);
        wds[j] = (unsigned)__half_as_ushort(h0) | ((unsigned)__half_as_ushort(h1) << 16);
    }
    g_x[idx] = make_uint4(wds[0], wds[1], wds[2], wds[3]);
}

// ---------------------------------------------------------------------------
// Weight fragment prep (fp16). word idx = cig*7168 + s*512 + ntp*128 + lane*4 + j
// j: 0 = nt(2ntp)   reg0, 1 = nt(2ntp)   reg1,
//    2 = nt(2ntp+1) reg0, 3 = nt(2ntp+1) reg1   (one LDS.128 serves 2 n-tiles)
// k = tap*8 + ci_local (tap padded to 28; tap 27 == zero)
// ---------------------------------------------------------------------------
__global__ void wfrag_kernel(const float* __restrict__ w) {
    int idx = blockIdx.x * 256 + threadIdx.x;
    if (idx >= 4*7168) return;
    int j    = idx & 3;
    int lane = (idx >> 2) & 31;
    int ntp  = (idx >> 7) & 3;
    int rest = idx >> 9;
    int s    = rest % 14;
    int cig  = rest / 14;
    int nt = ntp*2 + (j >> 1);
    int r  = j & 1;
    int q  = lane & 3;
    int n  = nt*8 + (lane >> 2);    // co
    unsigned word = 0;
    for (int e = 0; e < 2; e++) {
        int k   = s*16 + q*2 + r*8 + e;
        int cil = k & 7;
        int tap = k >> 3;
        float val = 0.f;
        if (tap < 27) val = w[(n*CIN + (cig*8 + cil))*27 + tap];
        word |= ((unsigned)__half_as_ushort(__float2half_rn(val))) << (16*e);
    }
    g_wfrag[idx] = word;
}

// aligns the profiled launch (harness+2, skip 5 => our index 3) onto conv
__global__ void noop_kernel() {}

// ---------------------------------------------------------------------------
__device__ __forceinline__ void mma16816(float (&c)[4], const unsigned (&a)[4],
                                         const unsigned b0, const unsigned b1) {
    asm volatile(
        "mma.sync.aligned.m16n8k16.row.col.f32.f16.f16.f32 "
        "{%0,%1,%2,%3}, {%4,%5,%6,%7}, {%8,%9}, {%0,%1,%2,%3};\n"
        : "+f"(c[0]), "+f"(c[1]), "+f"(c[2]), "+f"(c[3])
        : "r"(a[0]), "r"(a[1]), "r"(a[2]), "r"(a[3]), "r"(b0), "r"(b1));
}

// ---------------------------------------------------------------------------
// Conv3d 3x3x3 SAME + bias + tanh/sigmoid via implicit-GEMM HMMA (fp16 x fp16,
// fp32 accumulate). Block: 256 thr; tile 8h x 32w x 64co @ fixed (b,t).
// smem: fp16 halo [3tz][10y][34x][4 words] + weight frags for one cig.
// Per k-step: 8 A-LDS.32 + 4 B-LDS.128 feed 16 HMMA.
// ---------------------------------------------------------------------------
#define SX_WORDS (3*10*34*4)        /* 4080 words */
#define SWF_WORDS 7168
#define CONV_SMEM ((SX_WORDS + SWF_WORDS)*4)

__global__ __launch_bounds__(256, 2)
void conv_kernel(const float* __restrict__ bias) {
    extern __shared__ unsigned smw[];
    unsigned* s_x  = smw;
    unsigned* s_wf = smw + SX_WORDS;

    const int w0 = blockIdx.x * 32;
    const int h0 = blockIdx.y * 8;
    const int bz = blockIdx.z;
    const int b  = bz / T_;
    const int t  = bz % T_;
    const int tid  = threadIdx.x;
    const int lane = tid & 31;
    const int wi   = tid >> 5;      // warp -> output row
    const int g2   = lane >> 2;     // m-row within tile
    const int q2   = lane & 3;      // k / n low bits

    float acc[2][8][4];
    #pragma unroll
    for (int a2 = 0; a2 < 2; a2++)
        #pragma unroll
        for (int nt = 0; nt < 8; nt++)
            #pragma unroll
            for (int r = 0; r < 4; r++) acc[a2][nt][r] = 0.f;

    for (int cig = 0; cig < 4; cig++) {
        __syncthreads();
        // ---- halo load: uint4 copy of fp16 input ----
        for (int e = tid; e < 1020; e += 256) {
            int x  = e % 34; int r2 = e / 34;
            int y  = r2 % 10; int tz = r2 / 10;
            int tt = t + tz - 1, gh = h0 + y - 1, gw = w0 + x - 1;
            uint4 v = make_uint4(0u,0u,0u,0u);
            if (tt >= 0 && tt < T_ && gh >= 0 && gh < H_ && gw >= 0 && gw < W_) {
                size_t gi = ((size_t)((b*4 + cig)*T_ + tt)*H_ + gh)*W_ + gw;
                v = g_x[gi];
            }
            *(uint4*)(s_x + e*4) = v;
        }
        // ---- weight fragments for this cig ----
        {
            const uint4* src = (const uint4*)(g_wfrag + cig*SWF_WORDS);
            uint4* dst = (uint4*)s_wf;
            for (int li = tid; li < SWF_WORDS/4; li += 256) dst[li] = src[li];
        }
        __syncthreads();

        #pragma unroll
        for (int s = 0; s < 14; s++) {
            const int tapA = 2*s, tapB = 2*s + 1;
            const int ktA = tapA/9, rA = tapA%9, khA = rA/3, kwA = rA%3;
            const bool zB = (tapB == 27);
            const int ktB = zB ? 0 : tapB/9;
            const int rB  = zB ? 0 : tapB%9;
            const int khB = rB/3, kwB = rB%3;
            const int yA = wi + khA, yB = wi + khB;

            unsigned A[2][4];
            #pragma unroll
            for (int a2 = 0; a2 < 2; a2++) {
                const int xb = a2*16 + g2;
                const int iA0 = (((ktA*10 + yA)*34 + xb + kwA)*4) + q2;
                A[a2][0] = s_x[iA0];
                A[a2][1] = s_x[iA0 + 32];           /* +8 pixels */
                if (!zB) {
                    const int iB0 = (((ktB*10 + yB)*34 + xb + kwB)*4) + q2;
                    A[a2][2] = s_x[iB0];
                    A[a2][3] = s_x[iB0 + 32];       /* +8 pixels */
                } else {
                    A[a2][2] = 0u; A[a2][3] = 0u;
                }
            }
            #pragma unroll
            for (int ntp = 0; ntp < 4; ntp++) {
                uint4 B4 = *(const uint4*)(s_wf + (s*4 + ntp)*128 + lane*4);
                mma16816(acc[0][2*ntp],   A[0], B4.x, B4.y);
                mma16816(acc[1][2*ntp],   A[1], B4.x, B4.y);
                mma16816(acc[0][2*ntp+1], A[0], B4.z, B4.w);
                mma16816(acc[1][2*ntp+1], A[1], B4.z, B4.w);
            }
        }
    }

    // ---- epilogue: bias + activation ----
    const int h = h0 + wi;
    #pragma unroll
    for (int a2 = 0; a2 < 2; a2++) {
        const int wbase = w0 + a2*16 + g2;
        #pragma unroll
        for (int nt = 0; nt < 8; nt++) {
            const int co = nt*8 + q2*2;
            const float b0v = __ldg(bias + co), b1v = __ldg(bias + co + 1);
            float x00 = acc[a2][nt][0] + b0v;
            float x01 = acc[a2][nt][1] + b1v;
            float x10 = acc[a2][nt][2] + b0v;
            float x11 = acc[a2][nt][3] + b1v;
            float y00, y01, y10, y11;
            float* dst; int c_;
            if (nt < 4) {
                y00 = tanhf(x00); y01 = tanhf(x01); y10 = tanhf(x10); y11 = tanhf(x11);
                dst = g_Z; c_ = co;
            } else {
                y00 = 1.f/(1.f + __expf(-x00)); y01 = 1.f/(1.f + __expf(-x01));
                y10 = 1.f/(1.f + __expf(-x10)); y11 = 1.f/(1.f + __expf(-x11));
                dst = g_F; c_ = co - HID;
            }
            size_t base0 = ((size_t)((b*HID + c_)*T_ + t)*H_ + h)*W_ + wbase;
            dst[base0]     = y00; dst[base0 + 8] = y10;
            size_t base1 = base0 + CTHW;
            dst[base1]     = y01; dst[base1 + 8] = y11;
        }
    }
}

// ---------------------------------------------------------------------------
// Fused recurrence + channel attention, f32x2 edition (unchanged from R5).
// ---------------------------------------------------------------------------
#define RS   34
#define PS   1090
#define ATTN_SMEM (16*PS*4)

__global__ __launch_bounds__(256, 2)
void attn_kernel(const float* __restrict__ gamma, float* __restrict__ out) {
    extern __shared__ float sq[];    // [16][1090]
    const int w0 = blockIdx.x * 16;
    const int h  = blockIdx.y;
    const int b  = blockIdx.z;
    const int tid = threadIdx.x;

    // ---- phase 1: recurrence ----
    {
        const int px  = tid & 15;
        const int c16 = tid >> 4;
        #pragma unroll
        for (int ch = 0; ch < 2; ch++) {
            const int c = ch*16 + c16;
            size_t base = (size_t)((b*HID + c)*T_)*HW + (size_t)h*W_ + w0 + px;
            float hs = 0.f;
            float* dst = sq + px*PS + c*RS;
            #pragma unroll
            for (int t = 0; t < T_; t++) {
                float z = g_Z[base + (size_t)t*HW];
                float f = g_F[base + (size_t)t*HW];
                hs = f*hs + (1.f - f)*z;
                dst[t] = hs;
            }
            dst[31] = 0.f;   // pad slot read by float2 pair (30,31)
        }
    }
    __syncthreads();

    // ---- phase 2: attention ----
    const float gam = __ldg(gamma);
    const int lane = tid & 31;
    const int wid  = tid >> 5;

    for (int it = 0; it < 2; it++) {
        float* q = sq + (wid*2 + it)*PS;

        unsigned long long qrp[16];
        #pragma unroll
        for (int tp = 0; tp < 16; tp++)
            qrp[tp] = *(const unsigned long long*)&q[lane*RS + 2*tp];

        float a[32];
        #pragma unroll 4
        for (int d = 0; d < 32; d++) {
            const float* row = q + d*RS;
            unsigned long long acc2 = 0ULL;
            #pragma unroll
            for (int tp = 0; tp < 16; tp++)
                acc2 = ffma2(*(const unsigned long long*)&row[2*tp], qrp[tp], acc2);
            float lo, hi; unpack2(acc2, lo, hi);
            a[d] = lo + hi;
        }

        float m = a[0];
        #pragma unroll
        for (int d = 1; d < 32; d++) m = fmaxf(m, a[d]);
        float ssum = 0.f;
        #pragma unroll
        for (int d = 0; d < 32; d++) ssum += __expf(a[d] - m);

        #pragma unroll
        for (int d = 0; d < 32; d++) {
            float mc  = __shfl_sync(0xffffffffu, m,    d);
            float sc2 = __shfl_sync(0xffffffffu, ssum, d);
            a[d] = __expf(a[d] - mc) * (0.17677669529663687f / sc2); // /sqrt(32)
        }

        unsigned long long ahp[16];
        #pragma unroll
        for (int tp = 0; tp < 16; tp++) ahp[tp] = 0ULL;
        #pragma unroll 4
        for (int d = 0; d < 32; d++) {
            unsigned long long ad2 = pack2(a[d], a[d]);
            const float* row = q + d*RS;
            #pragma unroll
            for (int tp = 0; tp < 16; tp++)
                ahp[tp] = ffma2(*(const unsigned long long*)&row[2*tp], ad2, ahp[tp]);
        }

        __syncwarp();
        #pragma unroll
        for (int tp = 0; tp < 16; tp++) {
            float lo, hi; unpack2(ahp[tp], lo, hi);
            float2 own = *(float2*)&q[lane*RS + 2*tp];
            own.x = fmaf(gam, lo, own.x);
            own.y = fmaf(gam, hi, own.y);
            *(float2*)&q[lane*RS + 2*tp] = own;   // slot 31 garbage, never read
        }
        __syncwarp();
    }
    __syncthreads();

    // ---- phase 3: coalesced store to [B][C][T][H][W] ----
    for (int i = tid; i < 16*992; i += 256) {
        int wpx = i & 15;
        int ct  = i >> 4;
        int c   = ct / 31;
        int t2  = ct - c*31;
        out[((size_t)((b*HID + c)*T_ + t2)*H_ + h)*W_ + w0 + wpx] =
            sq[wpx*PS + c*RS + t2];
    }
}

// ---------------------------------------------------------------------------
extern "C" void kernel_launch(void* const* d_in, const int* in_sizes, int n_in,
                              void* d_out, int out_size) {
    const float* input  = (const float*)d_in[0];
    const float* conv_w = (const float*)d_in[1];
    const float* conv_b = (const float*)d_in[2];
    const float* gamma  = (const float*)d_in[3];
    float* out = (float*)d_out;

    xsplit_kernel<<<(NPIX + 255)/256, 256>>>(input);           // our idx 0
    wfrag_kernel<<<(4*7168 + 255)/256, 256>>>(conv_w);         // our idx 1
    noop_kernel<<<1, 32>>>();                                  // our idx 2

    cudaFuncSetAttribute(conv_kernel, cudaFuncAttributeMaxDynamicSharedMemorySize,
                         CONV_SMEM);
    dim3 cgrid(W_/32, H_/8, B_*T_);
    conv_kernel<<<cgrid, 256, CONV_SMEM>>>(conv_b);            // our idx 3 -> ncu

    cudaFuncSetAttribute(attn_kernel, cudaFuncAttributeMaxDynamicSharedMemorySize,
                         ATTN_SMEM);
    dim3 agrid(W_/16, H_, B_);
    attn_kernel<<<agrid, 256, ATTN_SMEM>>>(gamma, out);        // our idx 4
}

// round 8
// speedup vs baseline: 6.3089x; 1.1616x over previous
#include <cuda_runtime.h>
#include <cuda_fp16.h>
#include <math.h>

#define B_   4
#define CIN  32
#define HID  32
#define T_   31
#define H_   96
#define W_   96
#define HW   (H_*W_)          /* 9216 */
#define CTHW ((size_t)T_*HW)  /* per-channel stride 285696 */
#define NELEM (B_*HID*T_*HW)
#define NPIX  (B_*4*T_*H_*W_) /* b,cig,t,h,w = 4,571,136 */

// Scratch (device globals; no runtime allocation)
__device__ float g_Z[NELEM];                // tanh gate   [B][C][T][H][W]
__device__ float g_F[NELEM];                // sigmoid gate[B][C][T][H][W]
__device__ uint4 g_x[NPIX];                 // input fp16: pixel = 8 ci (4 fp16x2)
__device__ unsigned g_wfrag[4*14*4*32*4];   // fp16 weight fragments (2 nt / uint4)

// ---------------------------------------------------------------------------
// f32x2 packed-FMA helpers (Blackwell)
// ---------------------------------------------------------------------------
__device__ __forceinline__ unsigned long long ffma2(unsigned long long a,
                                                    unsigned long long b,
                                                    unsigned long long c) {
    unsigned long long d;
    asm("fma.rn.f32x2 %0, %1, %2, %3;" : "=l"(d) : "l"(a), "l"(b), "l"(c));
    return d;
}
__device__ __forceinline__ unsigned long long pack2(float lo, float hi) {
    unsigned long long r;
    asm("mov.b64 %0, {%1, %2};" : "=l"(r) : "f"(lo), "f"(hi));
    return r;
}
__device__ __forceinline__ void unpack2(unsigned long long v, float &lo, float &hi) {
    asm("mov.b64 {%0, %1}, %2;" : "=f"(lo), "=f"(hi) : "l"(v));
}

// cp.async 16B with zero-fill when pred==false (src-size=0 -> no global read)
__device__ __forceinline__ void cp16(unsigned* sdst, const void* gsrc, bool pred) {
    unsigned saddr = (unsigned)__cvta_generic_to_shared(sdst);
    int sb = pred ? 16 : 0;
    asm volatile("cp.async.cg.shared.global [%0], [%1], 16, %2;\n"
                 :: "r"(saddr), "l"(gsrc), "r"(sb) : "memory");
}

// ---------------------------------------------------------------------------
// Input prep: fp32 -> fp16x2, pixel = 8 ci packed into one uint4.
// ---------------------------------------------------------------------------
__global__ void xsplit_kernel(const float* __restrict__ in) {
    int idx = blockIdx.x * 256 + threadIdx.x;
    if (idx >= NPIX) return;
    int w = idx % W_; int r = idx / W_;
    int h = r % H_;   r /= H_;
    int t = r % T_;   r /= T_;
    int cig = r & 3;  int b = r >> 2;
    size_t base = ((size_t)((b*CIN + cig*8)*T_ + t)*H_ + h)*W_ + w;
    unsigned wds[4];
    #pragma unroll
    for (int j = 0; j < 4; j++) {
        __half h0 = __float2half_rn(in[base + (size_t)(2*j)*CTHW]);
        __half h1 = __float2half_rn(in[base + (size_t)(2*j+1)*CTHW]);
        wds[j] = (unsigned)__half_as_ushort(h0) | ((unsigned)__half_as_ushort(h1) << 16);
    }
    g_x[idx] = make_uint4(wds[0], wds[1], wds[2], wds[3]);
}

// ---------------------------------------------------------------------------
// Weight fragment prep (fp16). word idx = cig*7168 + s*512 + ntp*128 + lane*4 + j
// ---------------------------------------------------------------------------
__global__ void wfrag_kernel(const float* __restrict__ w) {
    int idx = blockIdx.x * 256 + threadIdx.x;
    if (idx >= 4*7168) return;
    int j    = idx & 3;
    int lane = (idx >> 2) & 31;
    int ntp  = (idx >> 7) & 3;
    int rest = idx >> 9;
    int s    = rest % 14;
    int cig  = rest / 14;
    int nt = ntp*2 + (j >> 1);
    int r  = j & 1;
    int q  = lane & 3;
    int n  = nt*8 + (lane >> 2);    // co
    unsigned word = 0;
    for (int e = 0; e < 2; e++) {
        int k   = s*16 + q*2 + r*8 + e;
        int cil = k & 7;
        int tap = k >> 3;
        float val = 0.f;
        if (tap < 27) val = w[(n*CIN + (cig*8 + cil))*27 + tap];
        word |= ((unsigned)__half_as_ushort(__float2half_rn(val))) << (16*e);
    }
    g_wfrag[idx] = word;
}

// aligns the profiled launch (harness+2, skip 5 => our index 3) onto conv
__global__ void noop_kernel() {}

// ---------------------------------------------------------------------------
__device__ __forceinline__ void mma16816(float (&c)[4], const unsigned (&a)[4],
                                         const unsigned b0, const unsigned b1) {
    asm volatile(
        "mma.sync.aligned.m16n8k16.row.col.f32.f16.f16.f32 "
        "{%0,%1,%2,%3}, {%4,%5,%6,%7}, {%8,%9}, {%0,%1,%2,%3};\n"
        : "+f"(c[0]), "+f"(c[1]), "+f"(c[2]), "+f"(c[3])
        : "r"(a[0]), "r"(a[1]), "r"(a[2]), "r"(a[3]), "r"(b0), "r"(b1));
}

// ---------------------------------------------------------------------------
// Conv3d 3x3x3 SAME + bias + tanh/sigmoid via implicit-GEMM HMMA (fp16, fp32
// accumulate), double-buffered cp.async pipeline over the 4 ci-groups.
// Block: 256 thr; tile 8h x 32w x 64co @ fixed (b,t).
// smem: 2 stages x (fp16 halo [3tz][10y][34x][4w] + weight frags).
// ---------------------------------------------------------------------------
#define SX_WORDS (3*10*34*4)        /* 4080 words */
#define SWF_WORDS 7168
#define STAGE_WORDS (SX_WORDS + SWF_WORDS)
#define CONV_SMEM (2*STAGE_WORDS*4) /* 89,984 bytes */

__global__ __launch_bounds__(256, 2)
void conv_kernel(const float* __restrict__ bias) {
    extern __shared__ unsigned smw[];

    const int w0 = blockIdx.x * 32;
    const int h0 = blockIdx.y * 8;
    const int bz = blockIdx.z;
    const int b  = bz / T_;
    const int t  = bz % T_;
    const int tid  = threadIdx.x;
    const int lane = tid & 31;
    const int wi   = tid >> 5;      // warp -> output row
    const int g2   = lane >> 2;     // m-row within tile
    const int q2   = lane & 3;      // k / n low bits

    float acc[2][8][4];
    #pragma unroll
    for (int a2 = 0; a2 < 2; a2++)
        #pragma unroll
        for (int nt = 0; nt < 8; nt++)
            #pragma unroll
            for (int r = 0; r < 4; r++) acc[a2][nt][r] = 0.f;

    // ---- async stage loader ----
    auto issue_load = [&](int cig, unsigned* s_x, unsigned* s_wf) {
        #pragma unroll
        for (int e0 = 0; e0 < 4; e0++) {
            int e = tid + e0*256;
            if (e < 1020) {
                int x  = e % 34; int r2 = e / 34;
                int y  = r2 % 10; int tz = r2 / 10;
                int tt = t + tz - 1, gh = h0 + y - 1, gw = w0 + x - 1;
                bool ok = (tt >= 0) & (tt < T_) & (gh >= 0) & (gh < H_) &
                          (gw >= 0) & (gw < W_);
                size_t gi = ok ? (((size_t)((b*4 + cig)*T_ + tt)*H_ + gh)*W_ + gw) : 0;
                cp16(s_x + e*4, g_x + gi, ok);
            }
        }
        const uint4* src = (const uint4*)(g_wfrag + cig*SWF_WORDS);
        #pragma unroll
        for (int li0 = 0; li0 < 7; li0++) {
            int li = tid + li0*256;
            cp16(s_wf + li*4, src + li, true);
        }
        asm volatile("cp.async.commit_group;\n" ::: "memory");
    };

    issue_load(0, smw, smw + SX_WORDS);

    for (int cig = 0; cig < 4; cig++) {
        unsigned* s_x  = smw + (cig & 1)*STAGE_WORDS;
        unsigned* s_wf = s_x + SX_WORDS;
        if (cig < 3) {
            unsigned* n_x = smw + ((cig + 1) & 1)*STAGE_WORDS;
            issue_load(cig + 1, n_x, n_x + SX_WORDS);
            asm volatile("cp.async.wait_group 1;\n" ::: "memory");
        } else {
            asm volatile("cp.async.wait_group 0;\n" ::: "memory");
        }
        __syncthreads();

        #pragma unroll
        for (int s = 0; s < 14; s++) {
            const int tapA = 2*s, tapB = 2*s + 1;
            const int ktA = tapA/9, rA = tapA%9, khA = rA/3, kwA = rA%3;
            const bool zB = (tapB == 27);
            const int ktB = zB ? 0 : tapB/9;
            const int rB  = zB ? 0 : tapB%9;
            const int khB = rB/3, kwB = rB%3;
            const int yA = wi + khA, yB = wi + khB;

            unsigned A[2][4];
            #pragma unroll
            for (int a2 = 0; a2 < 2; a2++) {
                const int xb = a2*16 + g2;
                const int iA0 = (((ktA*10 + yA)*34 + xb + kwA)*4) + q2;
                A[a2][0] = s_x[iA0];
                A[a2][1] = s_x[iA0 + 32];           /* +8 pixels */
                if (!zB) {
                    const int iB0 = (((ktB*10 + yB)*34 + xb + kwB)*4) + q2;
                    A[a2][2] = s_x[iB0];
                    A[a2][3] = s_x[iB0 + 32];       /* +8 pixels */
                } else {
                    A[a2][2] = 0u; A[a2][3] = 0u;
                }
            }
            #pragma unroll
            for (int ntp = 0; ntp < 4; ntp++) {
                uint4 B4 = *(const uint4*)(s_wf + (s*4 + ntp)*128 + lane*4);
                mma16816(acc[0][2*ntp],   A[0], B4.x, B4.y);
                mma16816(acc[1][2*ntp],   A[1], B4.x, B4.y);
                mma16816(acc[0][2*ntp+1], A[0], B4.z, B4.w);
                mma16816(acc[1][2*ntp+1], A[1], B4.z, B4.w);
            }
        }
        __syncthreads();
    }

    // ---- epilogue: bias + activation ----
    const int h = h0 + wi;
    #pragma unroll
    for (int a2 = 0; a2 < 2; a2++) {
        const int wbase = w0 + a2*16 + g2;
        #pragma unroll
        for (int nt = 0; nt < 8; nt++) {
            const int co = nt*8 + q2*2;
            const float b0v = __ldg(bias + co), b1v = __ldg(bias + co + 1);
            float x00 = acc[a2][nt][0] + b0v;
            float x01 = acc[a2][nt][1] + b1v;
            float x10 = acc[a2][nt][2] + b0v;
            float x11 = acc[a2][nt][3] + b1v;
            float y00, y01, y10, y11;
            float* dst; int c_;
            if (nt < 4) {
                y00 = tanhf(x00); y01 = tanhf(x01); y10 = tanhf(x10); y11 = tanhf(x11);
                dst = g_Z; c_ = co;
            } else {
                y00 = 1.f/(1.f + __expf(-x00)); y01 = 1.f/(1.f + __expf(-x01));
                y10 = 1.f/(1.f + __expf(-x10)); y11 = 1.f/(1.f + __expf(-x11));
                dst = g_F; c_ = co - HID;
            }
            size_t base0 = ((size_t)((b*HID + c_)*T_ + t)*H_ + h)*W_ + wbase;
            dst[base0]     = y00; dst[base0 + 8] = y10;
            size_t base1 = base0 + CTHW;
            dst[base1]     = y01; dst[base1 + 8] = y11;
        }
    }
}

// ---------------------------------------------------------------------------
// Fused recurrence + channel attention, f32x2 edition (unchanged).
// ---------------------------------------------------------------------------
#define RS   34
#define PS   1090
#define ATTN_SMEM (16*PS*4)

__global__ __launch_bounds__(256, 2)
void attn_kernel(const float* __restrict__ gamma, float* __restrict__ out) {
    extern __shared__ float sq[];    // [16][1090]
    const int w0 = blockIdx.x * 16;
    const int h  = blockIdx.y;
    const int b  = blockIdx.z;
    const int tid = threadIdx.x;

    // ---- phase 1: recurrence ----
    {
        const int px  = tid & 15;
        const int c16 = tid >> 4;
        #pragma unroll
        for (int ch = 0; ch < 2; ch++) {
            const int c = ch*16 + c16;
            size_t base = (size_t)((b*HID + c)*T_)*HW + (size_t)h*W_ + w0 + px;
            float hs = 0.f;
            float* dst = sq + px*PS + c*RS;
            #pragma unroll
            for (int t = 0; t < T_; t++) {
                float z = g_Z[base + (size_t)t*HW];
                float f = g_F[base + (size_t)t*HW];
                hs = f*hs + (1.f - f)*z;
                dst[t] = hs;
            }
            dst[31] = 0.f;   // pad slot read by float2 pair (30,31)
        }
    }
    __syncthreads();

    // ---- phase 2: attention ----
    const float gam = __ldg(gamma);
    const int lane = tid & 31;
    const int wid  = tid >> 5;

    for (int it = 0; it < 2; it++) {
        float* q = sq + (wid*2 + it)*PS;

        unsigned long long qrp[16];
        #pragma unroll
        for (int tp = 0; tp < 16; tp++)
            qrp[tp] = *(const unsigned long long*)&q[lane*RS + 2*tp];

        float a[32];
        #pragma unroll 4
        for (int d = 0; d < 32; d++) {
            const float* row = q + d*RS;
            unsigned long long acc2 = 0ULL;
            #pragma unroll
            for (int tp = 0; tp < 16; tp++)
                acc2 = ffma2(*(const unsigned long long*)&row[2*tp], qrp[tp], acc2);
            float lo, hi; unpack2(acc2, lo, hi);
            a[d] = lo + hi;
        }

        float m = a[0];
        #pragma unroll
        for (int d = 1; d < 32; d++) m = fmaxf(m, a[d]);
        float ssum = 0.f;
        #pragma unroll
        for (int d = 0; d < 32; d++) ssum += __expf(a[d] - m);

        #pragma unroll
        for (int d = 0; d < 32; d++) {
            float mc  = __shfl_sync(0xffffffffu, m,    d);
            float sc2 = __shfl_sync(0xffffffffu, ssum, d);
            a[d] = __expf(a[d] - mc) * (0.17677669529663687f / sc2); // /sqrt(32)
        }

        unsigned long long ahp[16];
        #pragma unroll
        for (int tp = 0; tp < 16; tp++) ahp[tp] = 0ULL;
        #pragma unroll 4
        for (int d = 0; d < 32; d++) {
            unsigned long long ad2 = pack2(a[d], a[d]);
            const float* row = q + d*RS;
            #pragma unroll
            for (int tp = 0; tp < 16; tp++)
                ahp[tp] = ffma2(*(const unsigned long long*)&row[2*tp], ad2, ahp[tp]);
        }

        __syncwarp();
        #pragma unroll
        for (int tp = 0; tp < 16; tp++) {
            float lo, hi; unpack2(ahp[tp], lo, hi);
            float2 own = *(float2*)&q[lane*RS + 2*tp];
            own.x = fmaf(gam, lo, own.x);
            own.y = fmaf(gam, hi, own.y);
            *(float2*)&q[lane*RS + 2*tp] = own;   // slot 31 garbage, never read
        }
        __syncwarp();
    }
    __syncthreads();

    // ---- phase 3: coalesced store to [B][C][T][H][W] ----
    for (int i = tid; i < 16*992; i += 256) {
        int wpx = i & 15;
        int ct  = i >> 4;
        int c   = ct / 31;
        int t2  = ct - c*31;
        out[((size_t)((b*HID + c)*T_ + t2)*H_ + h)*W_ + w0 + wpx] =
            sq[wpx*PS + c*RS + t2];
    }
}

// ---------------------------------------------------------------------------
extern "C" void kernel_launch(void* const* d_in, const int* in_sizes, int n_in,
                              void* d_out, int out_size) {
    const float* input  = (const float*)d_in[0];
    const float* conv_w = (const float*)d_in[1];
    const float* conv_b = (const float*)d_in[2];
    const float* gamma  = (const float*)d_in[3];
    float* out = (float*)d_out;

    xsplit_kernel<<<(NPIX + 255)/256, 256>>>(input);           // our idx 0
    wfrag_kernel<<<(4*7168 + 255)/256, 256>>>(conv_w);         // our idx 1
    noop_kernel<<<1, 32>>>();                                  // our idx 2

    cudaFuncSetAttribute(conv_kernel, cudaFuncAttributeMaxDynamicSharedMemorySize,
                         CONV_SMEM);
    dim3 cgrid(W_/32, H_/8, B_*T_);
    conv_kernel<<<cgrid, 256, CONV_SMEM>>>(conv_b);            // our idx 3 -> ncu

    cudaFuncSetAttribute(attn_kernel, cudaFuncAttributeMaxDynamicSharedMemorySize,
                         ATTN_SMEM);
    dim3 agrid(W_/16, H_, B_);
    attn_kernel<<<agrid, 256, ATTN_SMEM>>>(gamma, out);        // our idx 4
}